// round 1
// baseline (speedup 1.0000x reference)
#include <cuda_runtime.h>

// ---------------------------------------------------------------------------
// ChordProgressionLoss:
//   per row t: pm = OR(1 << (pred[t][n] % 12)), tm likewise from targets.
//   sim(t)   = (inter + 1e-6*(p+q) + 1.2e-11) / ((p+12e-6)*(q+12e-6))
//   d(p, i)  = 1 - i / (p + 3 - i + 1e-8)   (jaccard vs 3-note template)
//   maj(t)   = [d(pm_t,M0) + d(pm_{t+1},M1) + d(pm_{t+2},M2) + d(pm_{t+3},M0)]/4
//   loss = (1 - mean_t sim) + 0.5 * mean_w min(maj, mino)
// All divisions are 16-entry LUTs (p,q in 1..4, i in 0..3); windows via
// warp shuffles (each warp covers 32 rows, owns 29 windows).
// Deterministic: per-block partials -> single-block tree reduction.
// ---------------------------------------------------------------------------

#define MAXB 16384
__device__ float g_partials[2 * MAXB];

__device__ __forceinline__ unsigned pcbit(float f) {
    int iv = (int)f;                      // values are exact small ints (0..127)
    int d  = (iv * 43691) >> 19;          // floor(iv/12), exact for 0<=iv<4000
    int pc = iv - 12 * d;
    return 1u << pc;
}

__global__ __launch_bounds__(256) void chord_main(
    const float4* __restrict__ pred, const float4* __restrict__ targ,
    int T, int nWarps)
{
    __shared__ float sJac[32];   // [rep*16 + (p-1)*4 + i] = 1 - i/(p+3-i+1e-8)
    __shared__ float sSim[32];   // [rep*16 + (p-1)*4 + (q-1)] = 1/((p+12e-6)(q+12e-6))
    __shared__ float redS[8], redP[8];

    int tid = threadIdx.x;
    if (tid < 32) {
        int idx = tid & 15;
        int p = (idx >> 2) + 1;
        int i = idx & 3;
        sJac[tid] = 1.0f - (float)i / ((float)(p + 3 - i) + 1e-8f);
        int q = i + 1;
        sSim[tid] = 1.0f / (((float)p + 12e-6f) * ((float)q + 12e-6f));
    }
    __syncthreads();

    int lane = tid & 31;
    int wIdx = tid >> 5;
    float simAcc = 0.0f, penAcc = 0.0f;
    unsigned rep = (unsigned)(lane & 1) << 4;   // 2x table replication vs bank conflicts

    for (int wg = blockIdx.x * 8 + wIdx; wg < nWarps; wg += gridDim.x * 8) {
        int r = wg * 29 + lane;                 // warp covers rows [wg*29, wg*29+31]
        bool inR = (r < T);
        float4 pv = make_float4(0.f, 0.f, 0.f, 0.f);
        float4 tv = pv;
        if (inR) { pv = pred[r]; tv = targ[r]; }

        unsigned pm = pcbit(pv.x) | pcbit(pv.y) | pcbit(pv.z) | pcbit(pv.w);
        unsigned tm = pcbit(tv.x) | pcbit(tv.y) | pcbit(tv.z) | pcbit(tv.w);

        int p = __popc(pm);                     // 1..4 always (pm has >=1 bit)
        int q = __popc(tm);
        int inter = __popc(pm & tm);
        unsigned p4 = rep + ((unsigned)(p - 1) << 2);

        // similarity (exact closed form of the eps-normalized dot product)
        float num = fmaf(1e-6f, (float)(p + q), (float)inter + 1.2e-11f);
        float sim = num * sSim[p4 + (unsigned)(q - 1)];

        // jaccard distances vs the 6 distinct templates (M3==M0, m3==m0)
        float dM0 = sJac[p4 + __popc(pm & 0x091u)];   // (0,4,7)
        float dM1 = sJac[p4 + __popc(pm & 0x221u)];   // (5,9,0)
        float dM2 = sJac[p4 + __popc(pm & 0x884u)];   // (7,11,2)
        float dm0 = sJac[p4 + __popc(pm & 0x089u)];   // (0,3,7)
        float dm1 = sJac[p4 + __popc(pm & 0x121u)];   // (5,8,0)
        float dm2 = sJac[p4 + __popc(pm & 0x484u)];   // (7,10,2)

        // window sums via intra-warp neighbor gather (lanes 0..28 own windows)
        float maj = dM0 + __shfl_down_sync(0xffffffffu, dM1, 1)
                        + __shfl_down_sync(0xffffffffu, dM2, 2)
                        + __shfl_down_sync(0xffffffffu, dM0, 3);
        float mno = dm0 + __shfl_down_sync(0xffffffffu, dm1, 1)
                        + __shfl_down_sync(0xffffffffu, dm2, 2)
                        + __shfl_down_sync(0xffffffffu, dm0, 3);

        bool own = (lane < 29) && inR;
        if (own) simAcc += sim;
        if (own && (r <= T - 4)) penAcc += fminf(maj, mno);   // /4 deferred to epilogue
    }

    // deterministic block reduction
    #pragma unroll
    for (int o = 16; o; o >>= 1) {
        simAcc += __shfl_xor_sync(0xffffffffu, simAcc, o);
        penAcc += __shfl_xor_sync(0xffffffffu, penAcc, o);
    }
    if (lane == 0) { redS[wIdx] = simAcc; redP[wIdx] = penAcc; }
    __syncthreads();
    if (tid == 0) {
        float s = 0.f, pp = 0.f;
        #pragma unroll
        for (int k = 0; k < 8; k++) { s += redS[k]; pp += redP[k]; }
        g_partials[2 * blockIdx.x]     = s;
        g_partials[2 * blockIdx.x + 1] = pp;
    }
}

__global__ __launch_bounds__(256) void chord_final(float* __restrict__ out,
                                                   int T, int nBlocks)
{
    __shared__ double shS[256], shP[256];
    double s = 0.0, p = 0.0;
    for (int i = threadIdx.x; i < nBlocks; i += 256) {
        s += (double)g_partials[2 * i];
        p += (double)g_partials[2 * i + 1];
    }
    shS[threadIdx.x] = s;
    shP[threadIdx.x] = p;
    __syncthreads();
    #pragma unroll
    for (int o = 128; o; o >>= 1) {
        if (threadIdx.x < o) {
            shS[threadIdx.x] += shS[threadIdx.x + o];
            shP[threadIdx.x] += shP[threadIdx.x + o];
        }
        __syncthreads();
    }
    if (threadIdx.x == 0) {
        double simLoss = 1.0 - shS[0] / (double)T;
        // penAcc holds 4*min(maj,mino); 0.5 weight * /4 * mean over (T-3) windows
        double pen = (T > 3) ? (0.125 * shP[0] / (double)(T - 3)) : 0.0;
        out[0] = (float)(simLoss + pen);
    }
}

extern "C" void kernel_launch(void* const* d_in, const int* in_sizes, int n_in,
                              void* d_out, int out_size)
{
    const float4* pred = (const float4*)d_in[0];
    const float4* targ = (const float4*)d_in[1];
    int T1 = in_sizes[0] / 4;
    int T2 = in_sizes[1] / 4;
    int T = (T1 < T2) ? T1 : T2;

    int nWarps = (T + 28) / 29;           // each warp owns 29 rows/windows
    int blocks = (nWarps + 7) / 8;        // 8 warps per block
    if (blocks > MAXB) blocks = MAXB;     // grid-stride loop covers the rest
    if (blocks < 1) blocks = 1;

    chord_main<<<blocks, 256>>>(pred, targ, T, nWarps);
    chord_final<<<1, 256>>>((float*)d_out, T, blocks);
}

// round 2
// speedup vs baseline: 1.3769x; 1.3769x over previous
#include <cuda_runtime.h>

// ---------------------------------------------------------------------------
// ChordProgressionLoss — single fused persistent kernel.
//   per row t: pm = OR(1 << (pred[t][n] % 12)), tm likewise from targets.
//   sim(t)   = (inter + 1e-6*(p+q) + 1.2e-11) / ((p+12e-6)*(q+12e-6))
//   d(p, i)  = 1 - i/(p+3-i+1e-8)   (jaccard vs 3-note template)
//   loss = (1 - mean_t sim) + 0.5 * mean_w min(maj, mino)
// 16-entry reciprocal LUTs in smem (conflict-free: 32 words <-> 32 banks),
// windows via warp shuffles (warp covers 32 rows, owns 29 windows).
// Cross-block reduction fused via threadfence + atomic counter: the last
// block to finish sums all per-block partials in FIXED index order (double)
// -> fully deterministic, graph-capturable, self-resetting.
// ---------------------------------------------------------------------------

#define MAXB 1184   // 148 SMs x 8 blocks: exactly one resident wave

__device__ float        g_partials[2 * MAXB];
__device__ unsigned int g_count = 0;

__device__ __forceinline__ unsigned pcbit(float f) {
    int iv = (int)f;                      // values are exact small ints (0..127)
    int d  = (iv * 43691) >> 19;          // floor(iv/12), exact for 0<=iv<4000
    int pc = iv - 12 * d;
    return 1u << pc;
}

__global__ __launch_bounds__(256) void chord_fused(
    const float4* __restrict__ pred, const float4* __restrict__ targ,
    float* __restrict__ out, int T, int nWarps)
{
    __shared__ float sJac[32];   // [rep*16 + (p-1)*4 + i] = 1 - i/(p+3-i+1e-8)
    __shared__ float sSim[32];   // [rep*16 + (p-1)*4 + (q-1)] = 1/((p+12e-6)(q+12e-6))
    __shared__ float redS[8], redP[8];
    __shared__ bool  amLast;

    const int tid = threadIdx.x;
    if (tid < 32) {
        int idx = tid & 15;
        int p = (idx >> 2) + 1;
        int i = idx & 3;
        sJac[tid] = 1.0f - (float)i / ((float)(p + 3 - i) + 1e-8f);
        int q = i + 1;
        sSim[tid] = 1.0f / (((float)p + 12e-6f) * ((float)q + 12e-6f));
    }
    __syncthreads();

    const int lane = tid & 31;
    const int wIdx = tid >> 5;
    float simAcc = 0.0f, penAcc = 0.0f;
    const unsigned rep = (unsigned)(lane & 1) << 4;   // 2x replication (free)

    for (int wg = blockIdx.x * 8 + wIdx; wg < nWarps; wg += gridDim.x * 8) {
        int r = wg * 29 + lane;                 // warp covers rows [wg*29, +31]
        bool inR = (r < T);
        float4 pv = make_float4(0.f, 0.f, 0.f, 0.f);
        float4 tv = pv;
        if (inR) { pv = pred[r]; tv = targ[r]; }

        unsigned pm = pcbit(pv.x) | pcbit(pv.y) | pcbit(pv.z) | pcbit(pv.w);
        unsigned tm = pcbit(tv.x) | pcbit(tv.y) | pcbit(tv.z) | pcbit(tv.w);

        int p = __popc(pm);                     // 1..4 always
        int q = __popc(tm);
        int inter = __popc(pm & tm);
        unsigned p4 = rep + ((unsigned)(p - 1) << 2);

        float num = fmaf(1e-6f, (float)(p + q), (float)inter + 1.2e-11f);
        float sim = num * sSim[p4 + (unsigned)(q - 1)];

        float dM0 = sJac[p4 + __popc(pm & 0x091u)];   // (0,4,7)
        float dM1 = sJac[p4 + __popc(pm & 0x221u)];   // (5,9,0)
        float dM2 = sJac[p4 + __popc(pm & 0x884u)];   // (7,11,2)
        float dm0 = sJac[p4 + __popc(pm & 0x089u)];   // (0,3,7)
        float dm1 = sJac[p4 + __popc(pm & 0x121u)];   // (5,8,0)
        float dm2 = sJac[p4 + __popc(pm & 0x484u)];   // (7,10,2)

        float maj = dM0 + __shfl_down_sync(0xffffffffu, dM1, 1)
                        + __shfl_down_sync(0xffffffffu, dM2, 2)
                        + __shfl_down_sync(0xffffffffu, dM0, 3);
        float mno = dm0 + __shfl_down_sync(0xffffffffu, dm1, 1)
                        + __shfl_down_sync(0xffffffffu, dm2, 2)
                        + __shfl_down_sync(0xffffffffu, dm0, 3);

        bool own = (lane < 29) && inR;
        if (own) simAcc += sim;
        if (own && (r <= T - 4)) penAcc += fminf(maj, mno);   // /4 deferred
    }

    // per-block deterministic reduction
    #pragma unroll
    for (int o = 16; o; o >>= 1) {
        simAcc += __shfl_xor_sync(0xffffffffu, simAcc, o);
        penAcc += __shfl_xor_sync(0xffffffffu, penAcc, o);
    }
    if (lane == 0) { redS[wIdx] = simAcc; redP[wIdx] = penAcc; }
    __syncthreads();
    if (tid == 0) {
        float s = 0.f, pp = 0.f;
        #pragma unroll
        for (int k = 0; k < 8; k++) { s += redS[k]; pp += redP[k]; }
        g_partials[2 * blockIdx.x]     = s;
        g_partials[2 * blockIdx.x + 1] = pp;
        __threadfence();
        unsigned prev = atomicAdd(&g_count, 1u);
        amLast = (prev == gridDim.x - 1);
    }
    __syncthreads();

    // last block: final deterministic double-precision reduction + reset
    if (amLast) {
        __shared__ double shS[256], shP[256];
        double s = 0.0, pp = 0.0;
        int nB = gridDim.x;
        for (int i = tid; i < nB; i += 256) {
            s  += (double)g_partials[2 * i];
            pp += (double)g_partials[2 * i + 1];
        }
        shS[tid] = s;
        shP[tid] = pp;
        __syncthreads();
        #pragma unroll
        for (int o = 128; o; o >>= 1) {
            if (tid < o) { shS[tid] += shS[tid + o]; shP[tid] += shP[tid + o]; }
            __syncthreads();
        }
        if (tid == 0) {
            double simLoss = 1.0 - shS[0] / (double)T;
            double pen = (T > 3) ? (0.125 * shP[0] / (double)(T - 3)) : 0.0;
            out[0] = (float)(simLoss + pen);
            g_count = 0;   // self-reset for next graph replay
        }
    }
}

extern "C" void kernel_launch(void* const* d_in, const int* in_sizes, int n_in,
                              void* d_out, int out_size)
{
    const float4* pred = (const float4*)d_in[0];
    const float4* targ = (const float4*)d_in[1];
    int T1 = in_sizes[0] / 4;
    int T2 = in_sizes[1] / 4;
    int T = (T1 < T2) ? T1 : T2;

    int nWarps = (T + 28) / 29;           // each warp owns 29 rows/windows
    int blocks = (nWarps + 7) / 8;        // 8 warps per block
    if (blocks > MAXB) blocks = MAXB;     // persistent grid-stride covers rest
    if (blocks < 1) blocks = 1;

    chord_fused<<<blocks, 256>>>(pred, targ, (float*)d_out, T, nWarps);
}